// round 10
// baseline (speedup 1.0000x reference)
#include <cuda_runtime.h>
#include <cuda_bf16.h>
#include <cuda_fp16.h>
#include <cstdint>

#define NN   50000
#define IN_F 256
#define AD   128
#define NH   8
#define NE   1600000

// Scratch
__device__ __half        g_qh[(size_t)NN * AD];     // 12.8 MB  q fp16
__device__ __half        g_kh[(size_t)NN * AD];     // 12.8 MB  k fp16
__device__ float         g_sum[NN * NH];            // 1.6 MB
__device__ __nv_bfloat16 g_ah[(size_t)NN * IN_F];   // 25.6 MB  hi hi-part
__device__ __nv_bfloat16 g_al[(size_t)NN * IN_F];   // 25.6 MB  hi lo-part
__device__ __nv_bfloat16 g_wh[2 * AD * IN_F];       // 128 KB   Qw/Kw hi-part
__device__ __nv_bfloat16 g_wl[2 * AD * IN_F];       // 128 KB   Qw/Kw lo-part

// ---------------------------------------------------------------------------
// Prep: split hi and weights into bf16 hi/lo pairs; zero g_sum.
// ---------------------------------------------------------------------------
#define PREP_A   (NN * 64)            // 3,200,000 float4 of hi
#define PREP_W   (2 * AD * 64)        // 16,384 float4 of Qw|Kw
#define PREP_S   (NN * NH / 4)        // 100,000 float4 zeros
#define PREP_TOT (PREP_A + PREP_W + PREP_S)

__device__ __forceinline__ void split4(float4 v, uint2& hו, uint2& lo) {
    __nv_bfloat16 h[4], l[4];
    float xs[4] = {v.x, v.y, v.z, v.w};
#pragma unroll
    for (int t = 0; t < 4; t++) {
        h[t] = __float2bfloat16_rn(xs[t]);
        l[t] = __float2bfloat16_rn(xs[t] - __bfloat162float(h[t]));
    }
    hו = *(uint2*)h;
    lo = *(uint2*)l;
}

__global__ void prep_kernel(const float* __restrict__ hi,
                            const float* __restrict__ Qw,
                            const float* __restrict__ Kw) {
    int idx = blockIdx.x * blockDim.x + threadIdx.x;
    if (idx < PREP_A) {
        float4 v = ((const float4*)hi)[idx];
        uint2 h, l;
        split4(v, h, l);
        ((uint2*)g_ah)[idx] = h;
        ((uint2*)g_al)[idx] = l;
    } else if (idx < PREP_A + PREP_W) {
        int i2 = idx - PREP_A;
        int m  = i2 >> 13;                 // 0=Q, 1=K (8192 float4 each)
        int r  = i2 & 8191;
        float4 v = ((const float4*)(m ? Kw : Qw))[r];
        uint2 h, l;
        split4(v, h, l);
        ((uint2*)g_wh)[(size_t)m * 8192 + r] = h;
        ((uint2*)g_wl)[(size_t)m * 8192 + r] = l;
    } else if (idx < PREP_TOT) {
        int i3 = idx - PREP_A - PREP_W;
        ((float4*)g_sum)[i3] = make_float4(0.f, 0.f, 0.f, 0.f);
    }
}

// ---------------------------------------------------------------------------
// Tensor-core helpers
// ---------------------------------------------------------------------------
__device__ __forceinline__ void ldsm_x4(uint32_t& r0, uint32_t& r1,
                                        uint32_t& r2, uint32_t& r3,
                                        uint32_t addr) {
    asm volatile("ldmatrix.sync.aligned.m8n8.x4.shared.b16 {%0,%1,%2,%3}, [%4];"
                 : "=r"(r0), "=r"(r1), "=r"(r2), "=r"(r3) : "r"(addr));
}
__device__ __forceinline__ void ldsm_x2(uint32_t& r0, uint32_t& r1,
                                        uint32_t addr) {
    asm volatile("ldmatrix.sync.aligned.m8n8.x2.shared.b16 {%0,%1}, [%2];"
                 : "=r"(r0), "=r"(r1) : "r"(addr));
}
__device__ __forceinline__ void mma_bf16(float& c0, float& c1, float& c2, float& c3,
                                         uint32_t a0, uint32_t a1, uint32_t a2, uint32_t a3,
                                         uint32_t b0, uint32_t b1) {
    asm volatile("mma.sync.aligned.m16n8k16.row.col.f32.bf16.bf16.f32 "
                 "{%0,%1,%2,%3}, {%4,%5,%6,%7}, {%8,%9}, {%0,%1,%2,%3};"
                 : "+f"(c0), "+f"(c1), "+f"(c2), "+f"(c3)
                 : "r"(a0), "r"(a1), "r"(a2), "r"(a3), "r"(b0), "r"(b1));
}

// ---------------------------------------------------------------------------
// Projection GEMM: pre-split bf16 operands, register-prefetch pipeline.
// gridDim.y: 0 -> Q (g_qh), 1 -> K (g_kh). fp16 output.
// Block tile 128x128, K-chunk 32, 8 warps (4 M x 2 N).
// ---------------------------------------------------------------------------
#define KP 40   // padded k-stride (80B rows, 16B-aligned)

__global__ __launch_bounds__(256) void proj_mma_kernel(const float* __restrict__ Qb,
                                                       const float* __restrict__ Kb) {
    const int which = blockIdx.y;
    const float* bias = which ? Kb : Qb;
    __half* out = which ? g_kh : g_qh;
    const uint4* Agh = (const uint4*)g_ah;                       // 32 uint4/row
    const uint4* Agl = (const uint4*)g_al;
    const uint4* Wgh = (const uint4*)(g_wh + (size_t)which * AD * IN_F);
    const uint4* Wgl = (const uint4*)(g_wl + (size_t)which * AD * IN_F);

    __shared__ __nv_bfloat16 Ah[128][KP], Al[128][KP];
    __shared__ __nv_bfloat16 Wh[128][KP], Wl[128][KP];

    const int tid  = threadIdx.x;
    const int lane = tid & 31;
    const int wid  = tid >> 5;
    const int wm   = wid & 3;
    const int wn   = wid >> 2;
    const int m0   = blockIdx.x * 128;

    float c[2][8][4];
#pragma unroll
    for (int mt = 0; mt < 2; mt++)
#pragma unroll
        for (int nt = 0; nt < 8; nt++)
#pragma unroll
            for (int i = 0; i < 4; i++) c[mt][nt][i] = 0.0f;

    const int lrow  = tid >> 1;          // 0..127
    const int lhalf = tid & 1;           // 16-elem half of the 32-elem chunk
    int arow_g = m0 + lrow;
    if (arow_g >= NN) arow_g = NN - 1;   // clamp: garbage flows only to unstored rows

    // chunk row base in uint4 units: row*32 + ch*4 + lhalf*2 + j
    const size_t a_base = (size_t)arow_g * 32 + lhalf * 2;
    const size_t w_base = (size_t)lrow * 32 + lhalf * 2;

    const int a_row  = wm * 32 + (lane & 15);
    const int a_koff = (lane >> 4) * 8;
    const int b_row  = wn * 64 + (lane & 7);
    const int b_koff = ((lane >> 3) & 1) * 8;

    uint4 pah[2], pal[2], pwh[2], pwl[2];
#pragma unroll
    for (int j = 0; j < 2; j++) {        // prologue: chunk 0
        pah[j] = Agh[a_base + j];
        pal[j] = Agl[a_base + j];
        pwh[j] = Wgh[w_base + j];
        pwl[j] = Wgl[w_base + j];
    }

    for (int ch = 0; ch < 8; ch++) {
        // store prefetched tiles to smem
#pragma unroll
        for (int j = 0; j < 2; j++) {
            int col = lhalf * 16 + j * 8;
            *(uint4*)&Ah[lrow][col] = pah[j];
            *(uint4*)&Al[lrow][col] = pal[j];
            *(uint4*)&Wh[lrow][col] = pwh[j];
            *(uint4*)&Wl[lrow][col] = pwl[j];
        }
        __syncthreads();

        // prefetch next chunk
        if (ch < 7) {
            const size_t off = (size_t)(ch + 1) * 4;
#pragma unroll
            for (int j = 0; j < 2; j++) {
                pah[j] = Agh[a_base + off + j];
                pal[j] = Agl[a_base + off + j];
                pwh[j] = Wgh[w_base + off + j];
                pwl[j] = Wgl[w_base + off + j];
            }
        }

        // mma phase: 2 k-steps of 16
#pragma unroll
        for (int ks = 0; ks < 2; ks++) {
            const int k0 = ks * 16;
            uint32_t ah[2][4], al[2][4];
#pragma unroll
            for (int mt = 0; mt < 2; mt++) {
                uint32_t addr_h = (uint32_t)__cvta_generic_to_shared(
                    &Ah[a_row + mt * 16][k0 + a_koff]);
                ldsm_x4(ah[mt][0], ah[mt][1], ah[mt][2], ah[mt][3], addr_h);
                uint32_t addr_l = (uint32_t)__cvta_generic_to_shared(
                    &Al[a_row + mt * 16][k0 + a_koff]);
                ldsm_x4(al[mt][0], al[mt][1], al[mt][2], al[mt][3], addr_l);
            }
#pragma unroll
            for (int nt = 0; nt < 8; nt++) {
                uint32_t bh0, bh1, bl0, bl1;
                uint32_t baddr_h = (uint32_t)__cvta_generic_to_shared(
                    &Wh[b_row + nt * 8][k0 + b_koff]);
                ldsm_x2(bh0, bh1, baddr_h);
                uint32_t baddr_l = (uint32_t)__cvta_generic_to_shared(
                    &Wl[b_row + nt * 8][k0 + b_koff]);
                ldsm_x2(bl0, bl1, baddr_l);
#pragma unroll
                for (int mt = 0; mt < 2; mt++) {
                    mma_bf16(c[mt][nt][0], c[mt][nt][1], c[mt][nt][2], c[mt][nt][3],
                             ah[mt][0], ah[mt][1], ah[mt][2], ah[mt][3], bh0, bh1);
                    mma_bf16(c[mt][nt][0], c[mt][nt][1], c[mt][nt][2], c[mt][nt][3],
                             ah[mt][0], ah[mt][1], ah[mt][2], ah[mt][3], bl0, bl1);
                    mma_bf16(c[mt][nt][0], c[mt][nt][1], c[mt][nt][2], c[mt][nt][3],
                             al[mt][0], al[mt][1], al[mt][2], al[mt][3], bh0, bh1);
                }
            }
        }
        __syncthreads();
    }

    // epilogue: add bias, store fp16
#pragma unroll
    for (int nt = 0; nt < 8; nt++) {
        const int col = wn * 64 + nt * 8 + (lane & 3) * 2;
        const float b0 = __ldg(&bias[col]);
        const float b1 = __ldg(&bias[col + 1]);
#pragma unroll
        for (int mt = 0; mt < 2; mt++) {
            const int r0 = m0 + wm * 32 + mt * 16 + (lane >> 2);
            if (r0 < NN) {
                *(__half2*)&out[(size_t)r0 * AD + col] =
                    __floats2half2_rn(c[mt][nt][0] + b0, c[mt][nt][1] + b1);
            }
            const int r1 = r0 + 8;
            if (r1 < NN) {
                *(__half2*)&out[(size_t)r1 * AD + col] =
                    __floats2half2_rn(c[mt][nt][2] + b0, c[mt][nt][3] + b1);
            }
        }
    }
}

// ---------------------------------------------------------------------------
// Edge pass (unchanged): warp per 4 edges, fp16 gathers.
// ---------------------------------------------------------------------------
__global__ __launch_bounds__(256) void edge_kernel(const float* __restrict__ radial,
                                                   const int*  __restrict__ edge,
                                                   const float* __restrict__ Qrw,
                                                   const float* __restrict__ Qrb,
                                                   float* __restrict__ att,
                                                   float* __restrict__ prods) {
    const int lane = threadIdx.x & 31;
    const int gw   = (blockIdx.x * 256 + threadIdx.x) >> 5;
    const int e0   = gw * 4;

    const float4 w4 = ((const float4*)Qrw)[lane];
    const float4 b4 = ((const float4*)Qrb)[lane];

    int   src[4], dst[4];
    float rr[4];
#pragma unroll
    for (int j = 0; j < 4; j++) {
        src[j] = edge[e0 + j];
        dst[j] = edge[NE + e0 + j];
        rr[j]  = radial[e0 + j];
    }

    float2 qraw[4], kraw[4];
#pragma unroll
    for (int j = 0; j < 4; j++) {
        qraw[j] = *(const float2*)(g_qh + (size_t)src[j] * AD + lane * 4);
        kraw[j] = *(const float2*)(g_kh + (size_t)dst[j] * AD + lane * 4);
    }

    float p[4];
#pragma unroll
    for (int j = 0; j < 4; j++) {
        float2 q01 = __half22float2(*(__half2*)&qraw[j].x);
        float2 q23 = __half22float2(*(__half2*)&qraw[j].y);
        float2 k01 = __half22float2(*(__half2*)&kraw[j].x);
        float2 k23 = __half22float2(*(__half2*)&kraw[j].y);

        float sx = q01.x + fmaf(rr[j], w4.x, b4.x);
        float sy = q01.y + fmaf(rr[j], w4.y, b4.y);
        float sz = q23.x + fmaf(rr[j], w4.z, b4.z);
        float sw = q23.y + fmaf(rr[j], w4.w, b4.w);
        float t = sx * k01.x;
        t = fmaf(sy, k01.y, t);
        t = fmaf(sz, k23.x, t);
        t = fmaf(sw, k23.y, t);
        t += __shfl_xor_sync(0xffffffff, t, 1);
        t += __shfl_xor_sync(0xffffffff, t, 2);
        p[j] = t;
    }

    const int myj  = lane >> 3;
    const int srcl = (lane & 7) << 2;
    float pr = 0.f;
#pragma unroll
    for (int j = 0; j < 4; j++) {
        float t = __shfl_sync(0xffffffff, p[j], srcl);
        if (j == myj) pr = t;
    }
    pr *= 0.25f;

    const int obase = e0 * NH + lane;
    prods[obase] = pr;
    const float ex = __expf(pr);
    att[obase] = ex;

    int mysrc = src[0];
#pragma unroll
    for (int j = 1; j < 4; j++) if (j == myj) mysrc = src[j];
    atomicAdd(&g_sum[mysrc * NH + (lane & 7)], ex);
}

// ---------------------------------------------------------------------------
__global__ void norm_kernel(const int* __restrict__ edge,
                            float* __restrict__ att) {
    int i = blockIdx.x * blockDim.x + threadIdx.x;
    if (i < NE * NH / 4) {
        int e = i >> 1;
        int half = i & 1;
        const float4 s = *(const float4*)&g_sum[edge[e] * NH + half * 4];
        float4 a = ((float4*)att)[i];
        a.x /= s.x; a.y /= s.y; a.z /= s.z; a.w /= s.w;
        ((float4*)att)[i] = a;
    }
}

// ---------------------------------------------------------------------------
extern "C" void kernel_launch(void* const* d_in, const int* in_sizes, int n_in,
                              void* d_out, int out_size) {
    const float* hi     = (const float*)d_in[0];
    const float* radial = (const float*)d_in[1];
    const float* Qw     = (const float*)d_in[2];
    const float* Qb     = (const float*)d_in[3];
    const float* Qrw    = (const float*)d_in[4];
    const float* Qrb    = (const float*)d_in[5];
    const float* Kw     = (const float*)d_in[6];
    const float* Kb     = (const float*)d_in[7];
    const int*   edge   = (const int*)d_in[8];

    float* out   = (float*)d_out;
    float* att   = out;                       // [E, H]
    float* prods = out + (size_t)NE * NH;     // [E, H]

    prep_kernel<<<(PREP_TOT + 255) / 256, 256>>>(hi, Qw, Kw);
    dim3 pg((NN + 127) / 128, 2);
    proj_mma_kernel<<<pg, 256>>>(Qb, Kb);
    edge_kernel<<<NE / 32, 256>>>(radial, edge, Qrw, Qrb, att, prods);
    norm_kernel<<<(NE * NH / 4 + 255) / 256, 256>>>(edge, att);
}

// round 11
// speedup vs baseline: 1.2729x; 1.2729x over previous
#include <cuda_runtime.h>
#include <cuda_fp16.h>
#include <cstdint>

#define NN   50000
#define IN_F 256
#define AD   128
#define NH   8
#define NE   1600000

// Scratch
__device__ __half g_qh[(size_t)NN * AD];     // 12.8 MB  q fp16
__device__ __half g_kh[(size_t)NN * AD];     // 12.8 MB  k fp16
__device__ float  g_sum[NN * NH];            // 1.6 MB
__device__ __half g_hf[(size_t)NN * IN_F];   // 25.6 MB  hi fp16
__device__ __half g_wf[2 * AD * IN_F];       // 128 KB   Qw|Kw fp16

// ---------------------------------------------------------------------------
// Prep: convert hi and weights to fp16; zero g_sum. One streaming pass.
// ---------------------------------------------------------------------------
#define PREP_A   (NN * 64)            // hi float4 count
#define PREP_W   (2 * AD * 64)        // Qw|Kw float4 count
#define PREP_S   (NN * NH / 4)        // g_sum float4 zeros
#define PREP_TOT (PREP_A + PREP_W + PREP_S)

__device__ __forceinline__ uint2 cvt4(float4 v) {
    __half2 a = __floats2half2_rn(v.x, v.y);
    __half2 b = __floats2half2_rn(v.z, v.w);
    uint2 r;
    r.x = *(uint32_t*)&a;
    r.y = *(uint32_t*)&b;
    return r;
}

__global__ void prep_kernel(const float* __restrict__ hi,
                            const float* __restrict__ Qw,
                            const float* __restrict__ Kw) {
    int idx = blockIdx.x * blockDim.x + threadIdx.x;
    if (idx < PREP_A) {
        ((uint2*)g_hf)[idx] = cvt4(((const float4*)hi)[idx]);
    } else if (idx < PREP_A + PREP_W) {
        int i2 = idx - PREP_A;
        int m  = i2 >> 13;                 // 0=Q, 1=K (8192 float4 each)
        int r  = i2 & 8191;
        ((uint2*)g_wf)[(size_t)m * 8192 + r] = cvt4(((const float4*)(m ? Kw : Qw))[r]);
    } else if (idx < PREP_TOT) {
        int i3 = idx - PREP_A - PREP_W;
        ((float4*)g_sum)[i3] = make_float4(0.f, 0.f, 0.f, 0.f);
    }
}

// ---------------------------------------------------------------------------
// Tensor-core helpers (fp16 mma)
// ---------------------------------------------------------------------------
__device__ __forceinline__ void ldsm_x4(uint32_t& r0, uint32_t& r1,
                                        uint32_t& r2, uint32_t& r3,
                                        uint32_t addr) {
    asm volatile("ldmatrix.sync.aligned.m8n8.x4.shared.b16 {%0,%1,%2,%3}, [%4];"
                 : "=r"(r0), "=r"(r1), "=r"(r2), "=r"(r3) : "r"(addr));
}
__device__ __forceinline__ void ldsm_x2(uint32_t& r0, uint32_t& r1,
                                        uint32_t addr) {
    asm volatile("ldmatrix.sync.aligned.m8n8.x2.shared.b16 {%0,%1}, [%2];"
                 : "=r"(r0), "=r"(r1) : "r"(addr));
}
__device__ __forceinline__ void mma_f16(float& c0, float& c1, float& c2, float& c3,
                                        uint32_t a0, uint32_t a1, uint32_t a2, uint32_t a3,
                                        uint32_t b0, uint32_t b1) {
    asm volatile("mma.sync.aligned.m16n8k16.row.col.f32.f16.f16.f32 "
                 "{%0,%1,%2,%3}, {%4,%5,%6,%7}, {%8,%9}, {%0,%1,%2,%3};"
                 : "+f"(c0), "+f"(c1), "+f"(c2), "+f"(c3)
                 : "r"(a0), "r"(a1), "r"(a2), "r"(a3), "r"(b0), "r"(b1));
}

// ---------------------------------------------------------------------------
// Projection GEMM: single-pass fp16 mma, register-prefetch pipeline.
// gridDim.y: 0 -> Q (g_qh), 1 -> K (g_kh). fp16 output.
// Block tile 128x128, K-chunk 32, 8 warps (4 M x 2 N), warp tile 32x64.
// ---------------------------------------------------------------------------
#define KP 40   // padded k-stride (80B rows)

__global__ __launch_bounds__(256) void proj_mma_kernel(const float* __restrict__ Qb,
                                                       const float* __restrict__ Kb) {
    const int which = blockIdx.y;
    const float* bias = which ? Kb : Qb;
    __half* out = which ? g_kh : g_qh;
    const uint4* Ag = (const uint4*)g_hf;                        // 32 uint4/row
    const uint4* Wg = (const uint4*)(g_wf + (size_t)which * AD * IN_F);

    __shared__ __half As[128][KP], Ws[128][KP];

    const int tid  = threadIdx.x;
    const int lane = tid & 31;
    const int wid  = tid >> 5;
    const int wm   = wid & 3;
    const int wn   = wid >> 2;
    const int m0   = blockIdx.x * 128;

    float c[2][8][4];
#pragma unroll
    for (int mt = 0; mt < 2; mt++)
#pragma unroll
        for (int nt = 0; nt < 8; nt++)
#pragma unroll
            for (int i = 0; i < 4; i++) c[mt][nt][i] = 0.0f;

    const int lrow  = tid >> 1;          // 0..127
    const int lhalf = tid & 1;
    int arow_g = m0 + lrow;
    if (arow_g >= NN) arow_g = NN - 1;   // clamp: flows only to unstored rows

    // per-chunk: 32 fp16 = 64B = 4 uint4 per row; 2 threads/row -> 2 uint4 each
    const size_t a_base = (size_t)arow_g * 32 + lhalf * 2;
    const size_t w_base = (size_t)lrow * 32 + lhalf * 2;

    const int a_row  = wm * 32 + (lane & 15);
    const int a_koff = (lane >> 4) * 8;
    const int b_row  = wn * 64 + (lane & 7);
    const int b_koff = ((lane >> 3) & 1) * 8;

    uint4 pa[2], pw[2];
#pragma unroll
    for (int j = 0; j < 2; j++) {        // prologue: chunk 0
        pa[j] = Ag[a_base + j];
        pw[j] = Wg[w_base + j];
    }

    for (int ch = 0; ch < 8; ch++) {
        // store prefetched tiles to smem
#pragma unroll
        for (int j = 0; j < 2; j++) {
            int col = lhalf * 16 + j * 8;
            *(uint4*)&As[lrow][col] = pa[j];
            *(uint4*)&Ws[lrow][col] = pw[j];
        }
        __syncthreads();

        // prefetch next chunk (LDGs overlap the mma phase)
        if (ch < 7) {
            const size_t off = (size_t)(ch + 1) * 4;
#pragma unroll
            for (int j = 0; j < 2; j++) {
                pa[j] = Ag[a_base + off + j];
                pw[j] = Wg[w_base + off + j];
            }
        }

        // mma phase: 2 k-steps of 16
#pragma unroll
        for (int ks = 0; ks < 2; ks++) {
            const int k0 = ks * 16;
            uint32_t a[2][4];
#pragma unroll
            for (int mt = 0; mt < 2; mt++) {
                uint32_t addr = (uint32_t)__cvta_generic_to_shared(
                    &As[a_row + mt * 16][k0 + a_koff]);
                ldsm_x4(a[mt][0], a[mt][1], a[mt][2], a[mt][3], addr);
            }
#pragma unroll
            for (int nt = 0; nt < 8; nt++) {
                uint32_t b0, b1;
                uint32_t baddr = (uint32_t)__cvta_generic_to_shared(
                    &Ws[b_row + nt * 8][k0 + b_koff]);
                ldsm_x2(b0, b1, baddr);
#pragma unroll
                for (int mt = 0; mt < 2; mt++) {
                    mma_f16(c[mt][nt][0], c[mt][nt][1], c[mt][nt][2], c[mt][nt][3],
                            a[mt][0], a[mt][1], a[mt][2], a[mt][3], b0, b1);
                }
            }
        }
        __syncthreads();
    }

    // epilogue: add bias, store fp16
#pragma unroll
    for (int nt = 0; nt < 8; nt++) {
        const int col = wn * 64 + nt * 8 + (lane & 3) * 2;
        const float b0 = __ldg(&bias[col]);
        const float b1 = __ldg(&bias[col + 1]);
#pragma unroll
        for (int mt = 0; mt < 2; mt++) {
            const int r0 = m0 + wm * 32 + mt * 16 + (lane >> 2);
            if (r0 < NN) {
                *(__half2*)&out[(size_t)r0 * AD + col] =
                    __floats2half2_rn(c[mt][nt][0] + b0, c[mt][nt][1] + b1);
            }
            const int r1 = r0 + 8;
            if (r1 < NN) {
                *(__half2*)&out[(size_t)r1 * AD + col] =
                    __floats2half2_rn(c[mt][nt][2] + b0, c[mt][nt][3] + b1);
            }
        }
    }
}

// ---------------------------------------------------------------------------
// Edge pass (unchanged): warp per 4 edges, fp16 gathers.
// ---------------------------------------------------------------------------
__global__ __launch_bounds__(256) void edge_kernel(const float* __restrict__ radial,
                                                   const int*  __restrict__ edge,
                                                   const float* __restrict__ Qrw,
                                                   const float* __restrict__ Qrb,
                                                   float* __restrict__ att,
                                                   float* __restrict__ prods) {
    const int lane = threadIdx.x & 31;
    const int gw   = (blockIdx.x * 256 + threadIdx.x) >> 5;
    const int e0   = gw * 4;

    const float4 w4 = ((const float4*)Qrw)[lane];
    const float4 b4 = ((const float4*)Qrb)[lane];

    int   src[4], dst[4];
    float rr[4];
#pragma unroll
    for (int j = 0; j < 4; j++) {
        src[j] = edge[e0 + j];
        dst[j] = edge[NE + e0 + j];
        rr[j]  = radial[e0 + j];
    }

    float2 qraw[4], kraw[4];
#pragma unroll
    for (int j = 0; j < 4; j++) {
        qraw[j] = *(const float2*)(g_qh + (size_t)src[j] * AD + lane * 4);
        kraw[j] = *(const float2*)(g_kh + (size_t)dst[j] * AD + lane * 4);
    }

    float p[4];
#pragma unroll
    for (int j = 0; j < 4; j++) {
        float2 q01 = __half22float2(*(__half2*)&qraw[j].x);
        float2 q23 = __half22float2(*(__half2*)&qraw[j].y);
        float2 k01 = __half22float2(*(__half2*)&kraw[j].x);
        float2 k23 = __half22float2(*(__half2*)&kraw[j].y);

        float sx = q01.x + fmaf(rr[j], w4.x, b4.x);
        float sy = q01.y + fmaf(rr[j], w4.y, b4.y);
        float sz = q23.x + fmaf(rr[j], w4.z, b4.z);
        float sw = q23.y + fmaf(rr[j], w4.w, b4.w);
        float t = sx * k01.x;
        t = fmaf(sy, k01.y, t);
        t = fmaf(sz, k23.x, t);
        t = fmaf(sw, k23.y, t);
        t += __shfl_xor_sync(0xffffffff, t, 1);
        t += __shfl_xor_sync(0xffffffff, t, 2);
        p[j] = t;
    }

    const int myj  = lane >> 3;
    const int srcl = (lane & 7) << 2;
    float pr = 0.f;
#pragma unroll
    for (int j = 0; j < 4; j++) {
        float t = __shfl_sync(0xffffffff, p[j], srcl);
        if (j == myj) pr = t;
    }
    pr *= 0.25f;

    const int obase = e0 * NH + lane;
    prods[obase] = pr;
    const float ex = __expf(pr);
    att[obase] = ex;

    int mysrc = src[0];
#pragma unroll
    for (int j = 1; j < 4; j++) if (j == myj) mysrc = src[j];
    atomicAdd(&g_sum[mysrc * NH + (lane & 7)], ex);
}

// ---------------------------------------------------------------------------
__global__ void norm_kernel(const int* __restrict__ edge,
                            float* __restrict__ att) {
    int i = blockIdx.x * blockDim.x + threadIdx.x;
    if (i < NE * NH / 4) {
        int e = i >> 1;
        int half = i & 1;
        const float4 s = *(const float4*)&g_sum[edge[e] * NH + half * 4];
        float4 a = ((float4*)att)[i];
        a.x /= s.x; a.y /= s.y; a.z /= s.z; a.w /= s.w;
        ((float4*)att)[i] = a;
    }
}

// ---------------------------------------------------------------------------
extern "C" void kernel_launch(void* const* d_in, const int* in_sizes, int n_in,
                              void* d_out, int out_size) {
    const float* hi     = (const float*)d_in[0];
    const float* radial = (const float*)d_in[1];
    const float* Qw     = (const float*)d_in[2];
    const float* Qb     = (const float*)d_in[3];
    const float* Qrw    = (const float*)d_in[4];
    const float* Qrb    = (const float*)d_in[5];
    const float* Kw     = (const float*)d_in[6];
    const float* Kb     = (const float*)d_in[7];
    const int*   edge   = (const int*)d_in[8];

    float* out   = (float*)d_out;
    float* att   = out;                       // [E, H]
    float* prods = out + (size_t)NE * NH;     // [E, H]

    prep_kernel<<<(PREP_TOT + 255) / 256, 256>>>(hi, Qw, Kw);
    dim3 pg((NN + 127) / 128, 2);
    proj_mma_kernel<<<pg, 256>>>(Qb, Kb);
    edge_kernel<<<NE / 32, 256>>>(radial, edge, Qrw, Qrb, att, prods);
    norm_kernel<<<(NE * NH / 4 + 255) / 256, 256>>>(edge, att);
}

// round 13
// speedup vs baseline: 1.3226x; 1.0390x over previous
#include <cuda_runtime.h>
#include <cuda_fp16.h>
#include <cstdint>

#define NN   50000
#define IN_F 256
#define AD   128
#define NH   8
#define NE   1600000

// Scratch
__device__ __half g_qh[(size_t)NN * AD];     // 12.8 MB  q fp16
__device__ __half g_kh[(size_t)NN * AD];     // 12.8 MB  k fp16
__device__ float  g_sum[NN * NH];            // 1.6 MB
__device__ __half g_hf[(size_t)NN * IN_F];   // 25.6 MB  hi fp16
__device__ __half g_wf[2 * AD * IN_F];       // 128 KB   Qw|Kw fp16

// ---------------------------------------------------------------------------
// Prep: convert hi and weights to fp16; zero g_sum. One streaming pass.
// ---------------------------------------------------------------------------
#define PREP_A   (NN * 64)
#define PREP_W   (2 * AD * 64)
#define PREP_S   (NN * NH / 4)
#define PREP_TOT (PREP_A + PREP_W + PREP_S)

__device__ __forceinline__ uint2 cvt4(float4 v) {
    __half2 a = __floats2half2_rn(v.x, v.y);
    __half2 b = __floats2half2_rn(v.z, v.w);
    uint2 r;
    r.x = *(uint32_t*)&a;
    r.y = *(uint32_t*)&b;
    return r;
}

__global__ void prep_kernel(const float* __restrict__ hi,
                            const float* __restrict__ Qw,
                            const float* __restrict__ Kw) {
    int idx = blockIdx.x * blockDim.x + threadIdx.x;
    if (idx < PREP_A) {
        ((uint2*)g_hf)[idx] = cvt4(((const float4*)hi)[idx]);
    } else if (idx < PREP_A + PREP_W) {
        int i2 = idx - PREP_A;
        int m  = i2 >> 13;
        int r  = i2 & 8191;
        ((uint2*)g_wf)[(size_t)m * 8192 + r] = cvt4(((const float4*)(m ? Kw : Qw))[r]);
    } else if (idx < PREP_TOT) {
        int i3 = idx - PREP_A - PREP_W;
        ((float4*)g_sum)[i3] = make_float4(0.f, 0.f, 0.f, 0.f);
    }
}

// ---------------------------------------------------------------------------
// Tensor-core helpers (fp16 mma)
// ---------------------------------------------------------------------------
__device__ __forceinline__ void ldsm_x4(uint32_t& r0, uint32_t& r1,
                                        uint32_t& r2, uint32_t& r3,
                                        uint32_t addr) {
    asm volatile("ldmatrix.sync.aligned.m8n8.x4.shared.b16 {%0,%1,%2,%3}, [%4];"
                 : "=r"(r0), "=r"(r1), "=r"(r2), "=r"(r3) : "r"(addr));
}
__device__ __forceinline__ void ldsm_x2(uint32_t& r0, uint32_t& r1,
                                        uint32_t addr) {
    asm volatile("ldmatrix.sync.aligned.m8n8.x2.shared.b16 {%0,%1}, [%2];"
                 : "=r"(r0), "=r"(r1) : "r"(addr));
}
__device__ __forceinline__ void mma_f16(float& c0, float& c1, float& c2, float& c3,
                                        uint32_t a0, uint32_t a1, uint32_t a2, uint32_t a3,
                                        uint32_t b0, uint32_t b1) {
    asm volatile("mma.sync.aligned.m16n8k16.row.col.f32.f16.f16.f32 "
                 "{%0,%1,%2,%3}, {%4,%5,%6,%7}, {%8,%9}, {%0,%1,%2,%3};"
                 : "+f"(c0), "+f"(c1), "+f"(c2), "+f"(c3)
                 : "r"(a0), "r"(a1), "r"(a2), "r"(a3), "r"(b0), "r"(b1));
}

// ---------------------------------------------------------------------------
// Projection GEMM (unchanged from R11): single-pass fp16 mma, pipelined.
// ---------------------------------------------------------------------------
#define KP 40

__global__ __launch_bounds__(256) void proj_mma_kernel(const float* __restrict__ Qb,
                                                       const float* __restrict__ Kb) {
    const int which = blockIdx.y;
    const float* bias = which ? Kb : Qb;
    __half* out = which ? g_kh : g_qh;
    const uint4* Ag = (const uint4*)g_hf;
    const uint4* Wg = (const uint4*)(g_wf + (size_t)which * AD * IN_F);

    __shared__ __half As[128][KP], Ws[128][KP];

    const int tid  = threadIdx.x;
    const int lane = tid & 31;
    const int wid  = tid >> 5;
    const int wm   = wid & 3;
    const int wn   = wid >> 2;
    const int m0   = blockIdx.x * 128;

    float c[2][8][4];
#pragma unroll
    for (int mt = 0; mt < 2; mt++)
#pragma unroll
        for (int nt = 0; nt < 8; nt++)
#pragma unroll
            for (int i = 0; i < 4; i++) c[mt][nt][i] = 0.0f;

    const int lrow  = tid >> 1;
    const int lhalf = tid & 1;
    int arow_g = m0 + lrow;
    if (arow_g >= NN) arow_g = NN - 1;

    const size_t a_base = (size_t)arow_g * 32 + lhalf * 2;
    const size_t w_base = (size_t)lrow * 32 + lhalf * 2;

    const int a_row  = wm * 32 + (lane & 15);
    const int a_koff = (lane >> 4) * 8;
    const int b_row  = wn * 64 + (lane & 7);
    const int b_koff = ((lane >> 3) & 1) * 8;

    uint4 pa[2], pw[2];
#pragma unroll
    for (int j = 0; j < 2; j++) {
        pa[j] = Ag[a_base + j];
        pw[j] = Wg[w_base + j];
    }

    for (int ch = 0; ch < 8; ch++) {
#pragma unroll
        for (int j = 0; j < 2; j++) {
            int col = lhalf * 16 + j * 8;
            *(uint4*)&As[lrow][col] = pa[j];
            *(uint4*)&Ws[lrow][col] = pw[j];
        }
        __syncthreads();

        if (ch < 7) {
            const size_t off = (size_t)(ch + 1) * 4;
#pragma unroll
            for (int j = 0; j < 2; j++) {
                pa[j] = Ag[a_base + off + j];
                pw[j] = Wg[w_base + off + j];
            }
        }

#pragma unroll
        for (int ks = 0; ks < 2; ks++) {
            const int k0 = ks * 16;
            uint32_t a[2][4];
#pragma unroll
            for (int mt = 0; mt < 2; mt++) {
                uint32_t addr = (uint32_t)__cvta_generic_to_shared(
                    &As[a_row + mt * 16][k0 + a_koff]);
                ldsm_x4(a[mt][0], a[mt][1], a[mt][2], a[mt][3], addr);
            }
#pragma unroll
            for (int nt = 0; nt < 8; nt++) {
                uint32_t b0, b1;
                uint32_t baddr = (uint32_t)__cvta_generic_to_shared(
                    &Ws[b_row + nt * 8][k0 + b_koff]);
                ldsm_x2(b0, b1, baddr);
#pragma unroll
                for (int mt = 0; mt < 2; mt++) {
                    mma_f16(c[mt][nt][0], c[mt][nt][1], c[mt][nt][2], c[mt][nt][3],
                            a[mt][0], a[mt][1], a[mt][2], a[mt][3], b0, b1);
                }
            }
        }
        __syncthreads();
    }

#pragma unroll
    for (int nt = 0; nt < 8; nt++) {
        const int col = wn * 64 + nt * 8 + (lane & 3) * 2;
        const float b0 = __ldg(&bias[col]);
        const float b1 = __ldg(&bias[col + 1]);
#pragma unroll
        for (int mt = 0; mt < 2; mt++) {
            const int r0 = m0 + wm * 32 + mt * 16 + (lane >> 2);
            if (r0 < NN) {
                *(__half2*)&out[(size_t)r0 * AD + col] =
                    __floats2half2_rn(c[mt][nt][0] + b0, c[mt][nt][1] + b1);
            }
            const int r1 = r0 + 8;
            if (r1 < NN) {
                *(__half2*)&out[(size_t)r1 * AD + col] =
                    __floats2half2_rn(c[mt][nt][2] + b0, c[mt][nt][3] + b1);
            }
        }
    }
}

// ---------------------------------------------------------------------------
// Edge pass v2: WARP per 8 EDGES, paired-lane LDG.128.
// Half-warp (16 lanes) covers one 256B q/k row; one LDG.128 instruction
// fetches rows for TWO edges (lanes 0-15 -> edge 2s, 16-31 -> edge 2s+1).
// Lane owns 8 fp16 features (sub*8..sub*8+7); head h = lanes {2h, 2h+1}.
// ---------------------------------------------------------------------------
__global__ __launch_bounds__(256) void edge_kernel(const float* __restrict__ radial,
                                                   const int*  __restrict__ edge,
                                                   const float* __restrict__ Qrw,
                                                   const float* __restrict__ Qrb,
                                                   float* __restrict__ att,
                                                   float* __restrict__ prods) {
    const int lane = threadIdx.x & 31;
    const int gw   = (blockIdx.x * 256 + threadIdx.x) >> 5;
    const int e0   = gw * 8;                      // NE/8 warps exactly
    const int side = lane >> 4;                   // which edge of each pair
    const int sub  = lane & 15;                   // 16B feature block

    // Qrw/Qrb features [sub*8 .. sub*8+8) — constant per lane
    float w8[8], b8[8];
    {
        const float4* w4p = (const float4*)Qrw;
        const float4* b4p = (const float4*)Qrb;
        float4 wa = w4p[sub * 2], wb = w4p[sub * 2 + 1];
        float4 ba = b4p[sub * 2], bb = b4p[sub * 2 + 1];
        w8[0]=wa.x; w8[1]=wa.y; w8[2]=wa.z; w8[3]=wa.w;
        w8[4]=wb.x; w8[5]=wb.y; w8[6]=wb.z; w8[7]=wb.w;
        b8[0]=ba.x; b8[1]=ba.y; b8[2]=ba.z; b8[3]=ba.w;
        b8[4]=bb.x; b8[5]=bb.y; b8[6]=bb.z; b8[7]=bb.w;
    }

    // Per-slot meta: this lane's edge of each pair
    int   msrc[4], mdst[4];
    float mr[4];
#pragma unroll
    for (int s = 0; s < 4; s++) {
        int e = e0 + 2 * s + side;
        msrc[s] = edge[e];
        mdst[s] = edge[NE + e];
        mr[s]   = radial[e];
    }

    // 8 independent LDG.128 gathers (each instruction: 2 edges x 256B)
    uint4 qv[4], kv[4];
#pragma unroll
    for (int s = 0; s < 4; s++) {
        qv[s] = *(const uint4*)(g_qh + (size_t)msrc[s] * AD + sub * 8);
        kv[s] = *(const uint4*)(g_kh + (size_t)mdst[s] * AD + sub * 8);
    }

    float t[4];
#pragma unroll
    for (int s = 0; s < 4; s++) {
        const uint32_t* qw = (const uint32_t*)&qv[s];
        const uint32_t* kw = (const uint32_t*)&kv[s];
        float acc = 0.f;
        const float r = mr[s];
#pragma unroll
        for (int p = 0; p < 4; p++) {
            float2 q2 = __half22float2(*(const __half2*)&qw[p]);
            float2 k2 = __half22float2(*(const __half2*)&kw[p]);
            float s0 = q2.x + fmaf(r, w8[2 * p],     b8[2 * p]);
            float s1 = q2.y + fmaf(r, w8[2 * p + 1], b8[2 * p + 1]);
            acc = fmaf(s0, k2.x, acc);
            acc = fmaf(s1, k2.y, acc);
        }
        // combine the 2 lanes of each head (lanes 2h, 2h+1 within each half)
        acc += __shfl_xor_sync(0xffffffff, acc, 1);
        t[s] = acc;
    }

    // Output: 2 rounds of 32 contiguous values (edges e0+4r..e0+4r+3)
#pragma unroll
    for (int r = 0; r < 2; r++) {
        // lane -> (edge e0+4r+(lane>>3), head lane&7)
        // source: slot 2r + (lane>>4), lane ((lane>>3)&1)*16 + 2*(lane&7)
        const int l_src = ((lane >> 3) & 1) * 16 + 2 * (lane & 7);
        const float va = __shfl_sync(0xffffffff, t[2 * r],     l_src);
        const float vb = __shfl_sync(0xffffffff, t[2 * r + 1], l_src);
        const float pr = ((lane >> 4) ? vb : va) * 0.25f;     // / sqrt(DK)

        const int obase = (e0 + 4 * r) * NH + lane;
        prods[obase] = pr;
        const float ex = __expf(pr);
        att[obase] = ex;

        const int se = edge[e0 + 4 * r + (lane >> 3)];        // src of my edge
        atomicAdd(&g_sum[se * NH + (lane & 7)], ex);
    }
}

// ---------------------------------------------------------------------------
__global__ void norm_kernel(const int* __restrict__ edge,
                            float* __restrict__ att) {
    int i = blockIdx.x * blockDim.x + threadIdx.x;
    if (i < NE * NH / 4) {
        int e = i >> 1;
        int half = i & 1;
        const float4 s = *(const float4*)&g_sum[edge[e] * NH + half * 4];
        float4 a = ((float4*)att)[i];
        a.x /= s.x; a.y /= s.y; a.z /= s.z; a.w /= s.w;
        ((float4*)att)[i] = a;
    }
}

// ---------------------------------------------------------------------------
extern "C" void kernel_launch(void* const* d_in, const int* in_sizes, int n_in,
                              void* d_out, int out_size) {
    const float* hi     = (const float*)d_in[0];
    const float* radial = (const float*)d_in[1];
    const float* Qw     = (const float*)d_in[2];
    const float* Qb     = (const float*)d_in[3];
    const float* Qrw    = (const float*)d_in[4];
    const float* Qrb    = (const float*)d_in[5];
    const float* Kw     = (const float*)d_in[6];
    const float* Kb     = (const float*)d_in[7];
    const int*   edge   = (const int*)d_in[8];

    float* out   = (float*)d_out;
    float* att   = out;                       // [E, H]
    float* prods = out + (size_t)NE * NH;     // [E, H]

    prep_kernel<<<(PREP_TOT + 255) / 256, 256>>>(hi, Qw, Kw);
    dim3 pg((NN + 127) / 128, 2);
    proj_mma_kernel<<<pg, 256>>>(Qb, Kb);
    // NE/8 warps = 200000; 8 warps/block -> 25000 blocks (exact)
    edge_kernel<<<NE / 64, 256>>>(radial, edge, Qrw, Qrb, att, prods);
    norm_kernel<<<(NE * NH / 4 + 255) / 256, 256>>>(edge, att);
}

// round 14
// speedup vs baseline: 1.4375x; 1.0869x over previous
#include <cuda_runtime.h>
#include <cuda_fp16.h>
#include <cstdint>

#define NN   50000
#define IN_F 256
#define AD   128
#define NH   8
#define NE   1600000

// Scratch
__device__ __half g_qh[(size_t)NN * AD];     // 12.8 MB  q fp16
__device__ __half g_kh[(size_t)NN * AD];     // 12.8 MB  k fp16
__device__ float  g_sum[NN * NH];            // 1.6 MB
__device__ __half g_wf[2 * AD * IN_F];       // 128 KB   Qw|Kw fp16

// ---------------------------------------------------------------------------
// Prep-lite: convert Qw|Kw to fp16; zero g_sum.
// ---------------------------------------------------------------------------
#define PREP_W   (2 * AD * 64)        // 16384 float4
#define PREP_S   (NN * NH / 4)        // 100000 float4
#define PREP_TOT (PREP_W + PREP_S)

__device__ __forceinline__ uint2 cvt4(float4 v) {
    __half2 a = __floats2half2_rn(v.x, v.y);
    __half2 b = __floats2half2_rn(v.z, v.w);
    uint2 r;
    r.x = *(uint32_t*)&a;
    r.y = *(uint32_t*)&b;
    return r;
}

__global__ void prep_kernel(const float* __restrict__ Qw,
                            const float* __restrict__ Kw) {
    int idx = blockIdx.x * blockDim.x + threadIdx.x;
    if (idx < PREP_W) {
        int m = idx >> 13;                 // 0=Q rows 0-127, 1=K rows 128-255
        int r = idx & 8191;
        ((uint2*)g_wf)[(size_t)m * 8192 + r] = cvt4(((const float4*)(m ? Kw : Qw))[r]);
    } else if (idx < PREP_TOT) {
        ((float4*)g_sum)[idx - PREP_W] = make_float4(0.f, 0.f, 0.f, 0.f);
    }
}

// ---------------------------------------------------------------------------
// Tensor-core helpers (fp16 mma)
// ---------------------------------------------------------------------------
__device__ __forceinline__ void ldsm_x4(uint32_t& r0, uint32_t& r1,
                                        uint32_t& r2, uint32_t& r3,
                                        uint32_t addr) {
    asm volatile("ldmatrix.sync.aligned.m8n8.x4.shared.b16 {%0,%1,%2,%3}, [%4];"
                 : "=r"(r0), "=r"(r1), "=r"(r2), "=r"(r3) : "r"(addr));
}
__device__ __forceinline__ void ldsm_x2(uint32_t& r0, uint32_t& r1,
                                        uint32_t addr) {
    asm volatile("ldmatrix.sync.aligned.m8n8.x2.shared.b16 {%0,%1}, [%2];"
                 : "=r"(r0), "=r"(r1) : "r"(addr));
}
__device__ __forceinline__ void mma_f16(float& c0, float& c1, float& c2, float& c3,
                                        uint32_t a0, uint32_t a1, uint32_t a2, uint32_t a3,
                                        uint32_t b0, uint32_t b1) {
    asm volatile("mma.sync.aligned.m16n8k16.row.col.f32.f16.f16.f32 "
                 "{%0,%1,%2,%3}, {%4,%5,%6,%7}, {%8,%9}, {%0,%1,%2,%3};"
                 : "+f"(c0), "+f"(c1), "+f"(c2), "+f"(c3)
                 : "r"(a0), "r"(a1), "r"(a2), "r"(a3), "r"(b0), "r"(b1));
}

// ---------------------------------------------------------------------------
// Fused Q|K projection GEMM: C[m, 0:256] = hi[m,:] x [Qw;Kw]^T (+bias).
// A tile (hi) read fp32, converted in-kernel, loaded ONCE for both outputs.
// Block tile 128(M) x 256(N), K-chunk 32; 512 threads, 16 warps (4M x 4N),
// warp tile 32x64. Cols 0-127 -> g_qh, 128-255 -> g_kh. fp16 output.
// ---------------------------------------------------------------------------
#define KP 40

__global__ __launch_bounds__(512) void proj_mma_kernel(const float* __restrict__ hi,
                                                       const float* __restrict__ Qb,
                                                       const float* __restrict__ Kb) {
    const uint4* Wg = (const uint4*)g_wf;        // 256 rows x 32 uint4

    __shared__ __half As[128][KP];               // 128 x 32 per chunk
    __shared__ __half Ws[256][KP];               // 256 x 32 per chunk

    const int tid  = threadIdx.x;
    const int lane = tid & 31;
    const int wid  = tid >> 5;                   // 0..15
    const int wm   = wid & 3;                    // M: rows wm*32..+31
    const int wn   = wid >> 2;                   // N: cols wn*64..+63
    const int m0   = blockIdx.x * 128;

    float c[2][8][4];
#pragma unroll
    for (int mt = 0; mt < 2; mt++)
#pragma unroll
        for (int nt = 0; nt < 8; nt++)
#pragma unroll
            for (int i = 0; i < 4; i++) c[mt][nt][i] = 0.0f;

    // A loader: 4 threads/row, each 2 float4 (8 floats -> 8 fp16 = 1 uint4)
    const int alrow = tid >> 2;                  // 0..127
    const int alq   = tid & 3;                   // quarter of 32-float chunk row
    int arow_g = m0 + alrow;
    if (arow_g >= NN) arow_g = NN - 1;
    const float4* hi4 = (const float4*)hi;       // row stride 64 float4
    const size_t a_base = (size_t)arow_g * 64 + alq * 2;

    // W loader: 2 threads/row, each 2 uint4
    const int wlrow = tid >> 1;                  // 0..255
    const int wlh   = tid & 1;
    const size_t w_base = (size_t)wlrow * 32 + wlh * 2;

    const int a_row  = wm * 32 + (lane & 15);
    const int a_koff = (lane >> 4) * 8;
    const int b_row  = wn * 64 + (lane & 7);
    const int b_koff = ((lane >> 3) & 1) * 8;

    float4 pa0, pa1;
    uint4  pw0, pw1;
    pa0 = hi4[a_base];  pa1 = hi4[a_base + 1];
    pw0 = Wg[w_base];   pw1 = Wg[w_base + 1];

    for (int ch = 0; ch < 8; ch++) {
        // convert + store A; store W
        {
            uint2 h0 = cvt4(pa0), h1 = cvt4(pa1);
            uint4 v; v.x = h0.x; v.y = h0.y; v.z = h1.x; v.w = h1.y;
            *(uint4*)&As[alrow][alq * 8] = v;
            *(uint4*)&Ws[wlrow][wlh * 16]     = pw0;
            *(uint4*)&Ws[wlrow][wlh * 16 + 8] = pw1;
        }
        __syncthreads();

        // prefetch next chunk
        if (ch < 7) {
            const int kc4 = (ch + 1) * 8;
            pa0 = hi4[a_base + kc4];
            pa1 = hi4[a_base + kc4 + 1];
            pw0 = Wg[w_base + (ch + 1) * 4];
            pw1 = Wg[w_base + (ch + 1) * 4 + 1];
        }

        // mma: 2 k-steps of 16
#pragma unroll
        for (int ks = 0; ks < 2; ks++) {
            const int k0 = ks * 16;
            uint32_t a[2][4];
#pragma unroll
            for (int mt = 0; mt < 2; mt++) {
                uint32_t addr = (uint32_t)__cvta_generic_to_shared(
                    &As[a_row + mt * 16][k0 + a_koff]);
                ldsm_x4(a[mt][0], a[mt][1], a[mt][2], a[mt][3], addr);
            }
#pragma unroll
            for (int nt = 0; nt < 8; nt++) {
                uint32_t b0, b1;
                uint32_t baddr = (uint32_t)__cvta_generic_to_shared(
                    &Ws[b_row + nt * 8][k0 + b_koff]);
                ldsm_x2(b0, b1, baddr);
#pragma unroll
                for (int mt = 0; mt < 2; mt++) {
                    mma_f16(c[mt][nt][0], c[mt][nt][1], c[mt][nt][2], c[mt][nt][3],
                            a[mt][0], a[mt][1], a[mt][2], a[mt][3], b0, b1);
                }
            }
        }
        __syncthreads();
    }

    // epilogue: cols 0-127 -> g_qh with Qb; 128-255 -> g_kh with Kb
    __half* out        = (wn < 2) ? g_qh : g_kh;
    const float* bias  = (wn < 2) ? Qb   : Kb;
    const int colbase  = (wn & 1) * 64;          // within 128-col half
#pragma unroll
    for (int nt = 0; nt < 8; nt++) {
        const int col = colbase + nt * 8 + (lane & 3) * 2;
        const float b0 = __ldg(&bias[col]);
        const float b1 = __ldg(&bias[col + 1]);
#pragma unroll
        for (int mt = 0; mt < 2; mt++) {
            const int r0 = m0 + wm * 32 + mt * 16 + (lane >> 2);
            if (r0 < NN) {
                *(__half2*)&out[(size_t)r0 * AD + col] =
                    __floats2half2_rn(c[mt][nt][0] + b0, c[mt][nt][1] + b1);
            }
            const int r1 = r0 + 8;
            if (r1 < NN) {
                *(__half2*)&out[(size_t)r1 * AD + col] =
                    __floats2half2_rn(c[mt][nt][2] + b0, c[mt][nt][3] + b1);
            }
        }
    }
}

// ---------------------------------------------------------------------------
// Edge pass: warp per 8 edges, paired-lane LDG.128 (R13 layout).
// Writes ONLY prods + atomic sums; norm recomputes exp.
// ---------------------------------------------------------------------------
__global__ __launch_bounds__(256) void edge_kernel(const float* __restrict__ radial,
                                                   const int*  __restrict__ edge,
                                                   const float* __restrict__ Qrw,
                                                   const float* __restrict__ Qrb,
                                                   float* __restrict__ prods) {
    const int lane = threadIdx.x & 31;
    const int gw   = (blockIdx.x * 256 + threadIdx.x) >> 5;
    const int e0   = gw * 8;
    const int side = lane >> 4;
    const int sub  = lane & 15;

    float w8[8], b8[8];
    {
        const float4* w4p = (const float4*)Qrw;
        const float4* b4p = (const float4*)Qrb;
        float4 wa = w4p[sub * 2], wb = w4p[sub * 2 + 1];
        float4 ba = b4p[sub * 2], bb = b4p[sub * 2 + 1];
        w8[0]=wa.x; w8[1]=wa.y; w8[2]=wa.z; w8[3]=wa.w;
        w8[4]=wb.x; w8[5]=wb.y; w8[6]=wb.z; w8[7]=wb.w;
        b8[0]=ba.x; b8[1]=ba.y; b8[2]=ba.z; b8[3]=ba.w;
        b8[4]=bb.x; b8[5]=bb.y; b8[6]=bb.z; b8[7]=bb.w;
    }

    int   msrc[4], mdst[4];
    float mr[4];
#pragma unroll
    for (int s = 0; s < 4; s++) {
        int e = e0 + 2 * s + side;
        msrc[s] = edge[e];
        mdst[s] = edge[NE + e];
        mr[s]   = radial[e];
    }

    uint4 qv[4], kv[4];
#pragma unroll
    for (int s = 0; s < 4; s++) {
        qv[s] = *(const uint4*)(g_qh + (size_t)msrc[s] * AD + sub * 8);
        kv[s] = *(const uint4*)(g_kh + (size_t)mdst[s] * AD + sub * 8);
    }

    float t[4];
#pragma unroll
    for (int s = 0; s < 4; s++) {
        const uint32_t* qw = (const uint32_t*)&qv[s];
        const uint32_t* kw = (const uint32_t*)&kv[s];
        float acc = 0.f;
        const float r = mr[s];
#pragma unroll
        for (int p = 0; p < 4; p++) {
            float2 q2 = __half22float2(*(const __half2*)&qw[p]);
            float2 k2 = __half22float2(*(const __half2*)&kw[p]);
            float s0 = q2.x + fmaf(r, w8[2 * p],     b8[2 * p]);
            float s1 = q2.y + fmaf(r, w8[2 * p + 1], b8[2 * p + 1]);
            acc = fmaf(s0, k2.x, acc);
            acc = fmaf(s1, k2.y, acc);
        }
        acc += __shfl_xor_sync(0xffffffff, acc, 1);
        t[s] = acc;
    }

#pragma unroll
    for (int r = 0; r < 2; r++) {
        const int l_src = ((lane >> 3) & 1) * 16 + 2 * (lane & 7);
        const float va = __shfl_sync(0xffffffff, t[2 * r],     l_src);
        const float vb = __shfl_sync(0xffffffff, t[2 * r + 1], l_src);
        const float pr = ((lane >> 4) ? vb : va) * 0.25f;

        prods[(e0 + 4 * r) * NH + lane] = pr;
        const float ex = __expf(pr);
        const int se = edge[e0 + 4 * r + (lane >> 3)];
        atomicAdd(&g_sum[se * NH + (lane & 7)], ex);
    }
}

// ---------------------------------------------------------------------------
// Norm: att[e,h] = exp(prods[e,h]) / sum[src,h]  (prods L2-warm)
// ---------------------------------------------------------------------------
__global__ void norm_kernel(const int* __restrict__ edge,
                            const float* __restrict__ prods,
                            float* __restrict__ att) {
    int i = blockIdx.x * blockDim.x + threadIdx.x;
    if (i < NE * NH / 4) {
        int e = i >> 1;
        int half = i & 1;
        const float4 s = *(const float4*)&g_sum[edge[e] * NH + half * 4];
        float4 p = ((const float4*)prods)[i];
        float4 a;
        a.x = __expf(p.x) / s.x;
        a.y = __expf(p.y) / s.y;
        a.z = __expf(p.z) / s.z;
        a.w = __expf(p.w) / s.w;
        ((float4*)att)[i] = a;
    }
}

// ---------------------------------------------------------------------------
extern "C" void kernel_launch(void* const* d_in, const int* in_sizes, int n_in,
                              void* d_out, int out_size) {
    const float* hi     = (const float*)d_in[0];
    const float* radial = (const float*)d_in[1];
    const float* Qw     = (const float*)d_in[2];
    const float* Qb     = (const float*)d_in[3];
    const float* Qrw    = (const float*)d_in[4];
    const float* Qrb    = (const float*)d_in[5];
    const float* Kw     = (const float*)d_in[6];
    const float* Kb     = (const float*)d_in[7];
    const int*   edge   = (const int*)d_in[8];

    float* out   = (float*)d_out;
    float* att   = out;                       // [E, H]
    float* prods = out + (size_t)NE * NH;     // [E, H]

    prep_kernel<<<(PREP_TOT + 255) / 256, 256>>>(Qw, Kw);
    proj_mma_kernel<<<(NN + 127) / 128, 512>>>(hi, Qb, Kb);
    edge_kernel<<<NE / 64, 256>>>(radial, edge, Qrw, Qrb, prods);
    norm_kernel<<<(NE * NH / 4 + 255) / 256, 256>>>(edge, prods, att);
}